// round 12
// baseline (speedup 1.0000x reference)
#include <cuda_runtime.h>

#define C_    256
#define B_    4
#define N_    4096
#define EPSF  1e-3f
#define LOG2E 1.4426950408889634f
#define GCH   128    // gap partial chunks per batch
#define ABL   111    // attention blocks per batch (111*37 >= 4096, 444 = 148*3)
#define ARPB  37     // attention rows per block

// ---- scratch (device globals, no allocations) ----
__device__ float g_partial[B_ * GCH * C_];
__device__ float g_mv[B_ * 16 * 3 * C_];    // matvec partials [b][seg][m][c]
__device__ float g_wf[B_ * C_ * 3];
__device__ float g_cf[B_ * 3];
__device__ float g_qs[B_ * N_];
__device__ float g_ks[B_ * N_];
__device__ float g_vs[B_ * N_];
__device__ unsigned g_kmax_u[B_];
__device__ unsigned g_kmin_u[B_];

__device__ __forceinline__ float ex2f(float x) {
    float r;
    asm("ex2.approx.ftz.f32 %0, %1;" : "=f"(r) : "f"(x));
    return r;
}
__device__ __forceinline__ unsigned encf(float f) {
    unsigned u = __float_as_uint(f);
    return (u & 0x80000000u) ? ~u : (u | 0x80000000u);
}
__device__ __forceinline__ float decf(unsigned u) {
    return __uint_as_float((u & 0x80000000u) ? (u ^ 0x80000000u) : ~u);
}
__device__ __forceinline__ void l2_prefetch(const void* p) {
    asm volatile("prefetch.global.L2 [%0];" :: "l"(p));
}

// ---------------------------------------------------------------------------
// K1: GAP partials. grid (GCH, B), 256 thr. Triggers PDL at entry so k_mv's
// weight preload overlaps this kernel.
// ---------------------------------------------------------------------------
__global__ void k_gap(const float* __restrict__ x,
                      const float* __restrict__ wq, const float* __restrict__ wk,
                      const float* __restrict__ wv, const float* __restrict__ wp) {
    cudaTriggerProgrammaticLaunchCompletion();
    __shared__ float4 sh[4][64];
    int b = blockIdx.y, blk = blockIdx.x, t = threadIdx.x;
    if (blk == 0 && b == 0 && t < B_) {
        g_kmax_u[t] = 0u;
        g_kmin_u[t] = 0xffffffffu;
    }
    int c4 = t & 63, rs = t >> 6;
    const float4* xp = (const float4*)(x + (size_t)b * N_ * C_);
    float4 s = make_float4(0.f, 0.f, 0.f, 0.f);
#pragma unroll
    for (int i = 0; i < 8; i++) {
        int row = blk * 32 + rs + 4 * i;
        float4 a = xp[(size_t)row * 64 + c4];
        s.x += a.x; s.y += a.y; s.z += a.z; s.w += a.w;
    }
    sh[rs][c4] = s;
    __syncthreads();
    if (t < 64) {
        float4 a = sh[0][t], bb = sh[1][t], c = sh[2][t], d = sh[3][t];
        float4 r;
        r.x = a.x + bb.x + c.x + d.x;
        r.y = a.y + bb.y + c.y + d.y;
        r.z = a.z + bb.z + c.z + d.z;
        r.w = a.w + bb.w + c.w + d.w;
        ((float4*)(g_partial + (size_t)(b * GCH + blk) * C_))[t] = r;
    }
}

// ---------------------------------------------------------------------------
// K2: gap-final + BN + q/k/v matvec PARTIALS. grid (16, B), 256 thr.
// PDL: weight rows preloaded into REGISTERS before the dependency sync, so
// the 768KB weight read overlaps k_gap.
// ---------------------------------------------------------------------------
__global__ void __launch_bounds__(256) k_mv(
        const float* __restrict__ ca_g, const float* __restrict__ ca_b,
        const float* __restrict__ ca_m, const float* __restrict__ ca_v,
        const float* __restrict__ wq,   const float* __restrict__ wk,
        const float* __restrict__ wv) {
    __shared__ float4 red[4][65];
    __shared__ float sh_gn[16];
    int seg = blockIdx.x, b = blockIdx.y, t = threadIdx.x;
    int u = t & 63, r2 = t >> 6;
    float* rb = (float*)red;

    cudaTriggerProgrammaticLaunchCompletion();

    // ---- pre-sync: weight loads into registers (independent of k_gap) ----
    float4 wqr[4], wkr[4], wvr[4];
#pragma unroll
    for (int i = 0; i < 4; i++) {
        int c = seg * 16 + r2 * 4 + i;
        wqr[i] = ((const float4*)(wq + (size_t)c * C_))[u];
        wkr[i] = ((const float4*)(wk + (size_t)c * C_))[u];
        wvr[i] = ((const float4*)(wv + (size_t)c * C_))[u];
    }

    cudaGridDependencySynchronize();

    // gap final for this segment's 16 channels: thread (c_l, piece)
    {
        int c_l = t >> 4, piece = t & 15;
        float s = 0.f;
#pragma unroll
        for (int j = 0; j < 8; j++)
            s += g_partial[(size_t)(b * GCH + piece * 8 + j) * C_ + seg * 16 + c_l];
        rb[c_l * 16 + piece] = s;
    }
    __syncthreads();
    if (t < 16) {
        float ss = 0.f;
#pragma unroll
        for (int p = 0; p < 16; p++) ss += rb[t * 16 + p];
        float gap = ss * (1.f / N_);
        int c = seg * 16 + t;
        sh_gn[t] = (gap - ca_m[c]) * rsqrtf(ca_v[c] + EPSF) * ca_g[c] + ca_b[c];
    }
    __syncthreads();

    // matvec partials with register-resident weights
    float4 q4 = make_float4(0, 0, 0, 0), k4 = q4, v4 = q4;
#pragma unroll
    for (int i = 0; i < 4; i++) {
        float gg = sh_gn[r2 * 4 + i];
        q4.x = fmaf(gg, wqr[i].x, q4.x); q4.y = fmaf(gg, wqr[i].y, q4.y);
        q4.z = fmaf(gg, wqr[i].z, q4.z); q4.w = fmaf(gg, wqr[i].w, q4.w);
        k4.x = fmaf(gg, wkr[i].x, k4.x); k4.y = fmaf(gg, wkr[i].y, k4.y);
        k4.z = fmaf(gg, wkr[i].z, k4.z); k4.w = fmaf(gg, wkr[i].w, k4.w);
        v4.x = fmaf(gg, wvr[i].x, v4.x); v4.y = fmaf(gg, wvr[i].y, v4.y);
        v4.z = fmaf(gg, wvr[i].z, v4.z); v4.w = fmaf(gg, wvr[i].w, v4.w);
    }
    float* mv = g_mv + (size_t)(b * 16 + seg) * 3 * C_;
    __syncthreads();
    red[r2][u] = q4; __syncthreads();
    if (t < 64) {
        float4 a = red[0][t], bb = red[1][t], c = red[2][t], d = red[3][t];
        ((float4*)mv)[t] = make_float4(a.x + bb.x + c.x + d.x, a.y + bb.y + c.y + d.y,
                                       a.z + bb.z + c.z + d.z, a.w + bb.w + c.w + d.w);
    }
    __syncthreads();
    red[r2][u] = k4; __syncthreads();
    if (t < 64) {
        float4 a = red[0][t], bb = red[1][t], c = red[2][t], d = red[3][t];
        ((float4*)(mv + C_))[t] = make_float4(a.x + bb.x + c.x + d.x, a.y + bb.y + c.y + d.y,
                                              a.z + bb.z + c.z + d.z, a.w + bb.w + c.w + d.w);
    }
    __syncthreads();
    red[r2][u] = v4; __syncthreads();
    if (t < 64) {
        float4 a = red[0][t], bb = red[1][t], c = red[2][t], d = red[3][t];
        ((float4*)(mv + 2 * C_))[t] = make_float4(a.x + bb.x + c.x + d.x, a.y + bb.y + c.y + d.y,
                                                  a.z + bb.z + c.z + d.z, a.w + bb.w + c.w + d.w);
    }
}

// ---------------------------------------------------------------------------
// K3: finalize channel attention. grid B, 1024 thr.
// PDL: prefetches all of wp into L2 pre-sync.
// ---------------------------------------------------------------------------
__global__ void __launch_bounds__(1024) k_fin(
        const float* __restrict__ wp,
        const float* __restrict__ bn_g, const float* __restrict__ bn_b,
        const float* __restrict__ bn_m, const float* __restrict__ bn_v,
        const float* __restrict__ wqkv) {
    __shared__ float4 red[16][65];
    __shared__ float sh_q[C_], sh_k[C_], sh_v[C_];
    __shared__ float sh_att[C_], sh_cm[C_], sh_d[C_];
    __shared__ float sh_mx[8], sh_mn[8], sh_scal[4];
    float* rbuf = (float*)red;
    int*   ibuf = (int*)red;
    int b = blockIdx.x, t = threadIdx.x;
    int lane = t & 31, wid = t >> 5;
    int col = t & 255, seg = t >> 8;
    int u = t & 63, r = t >> 6;

    cudaTriggerProgrammaticLaunchCompletion();
    // pre-sync: warm L2 with wp (256KB = 2048 lines; 2 per thread)
    l2_prefetch(wp + (size_t)(2 * t) * 32);
    l2_prefetch(wp + (size_t)(2 * t + 1) * 32);
    cudaGridDependencySynchronize();

    // ---- reduce q/k/v partials over 16 segments, spread over 4 ----
    {
        float qf = 0.f, kf = 0.f, vf = 0.f;
#pragma unroll
        for (int s2 = 0; s2 < 4; s2++) {
            const float* mv = g_mv + (size_t)(b * 16 + seg * 4 + s2) * 3 * C_;
            qf += mv[col]; kf += mv[C_ + col]; vf += mv[2 * C_ + col];
        }
        rbuf[t] = qf; rbuf[1024 + t] = kf; rbuf[2048 + t] = vf;
    }
    __syncthreads();
    if (t < 256) {
        sh_q[t] = rbuf[t] + rbuf[t + 256] + rbuf[t + 512] + rbuf[t + 768];
        sh_k[t] = rbuf[1024 + t] + rbuf[1024 + t + 256] + rbuf[1024 + t + 512] + rbuf[1024 + t + 768];
        sh_v[t] = rbuf[2048 + t] + rbuf[2048 + t + 256] + rbuf[2048 + t + 512] + rbuf[2048 + t + 768];
    }
    __syncthreads();

    // ---- k min/max ----
    if (t < 256) {
        float kk = sh_k[t];
        float mx = kk, mn = kk;
#pragma unroll
        for (int o = 16; o > 0; o >>= 1) {
            mx = fmaxf(mx, __shfl_xor_sync(0xffffffffu, mx, o));
            mn = fminf(mn, __shfl_xor_sync(0xffffffffu, mn, o));
        }
        if (lane == 0) { sh_mx[wid] = mx; sh_mn[wid] = mn; }
    }
    __syncthreads();
    if (t == 0) {
        float mx = sh_mx[0], mn = sh_mn[0];
        for (int i = 1; i < 8; i++) { mx = fmaxf(mx, sh_mx[i]); mn = fminf(mn, sh_mn[i]); }
        sh_scal[0] = mx; sh_scal[1] = mn;
    }
    __syncthreads();

    // ---- channel softmax, spread over 4 segments ----
    {
        float q = sh_q[col];
        float m = (q >= 0.f) ? q * sh_scal[0] : q * sh_scal[1];
        float c1 = q * LOG2E, mb = m * LOG2E;
        float num = 0.f, den = 0.f;
#pragma unroll 8
        for (int j = seg * 64; j < seg * 64 + 64; j++) {
            float e = ex2f(fmaf(c1, sh_k[j], -mb));
            den += e;
            num = fmaf(e, sh_v[j], num);
        }
        rbuf[t] = num; rbuf[2048 + t] = den;
    }
    __syncthreads();
    if (t < 256) {
        float num = rbuf[t] + rbuf[t + 256] + rbuf[t + 512] + rbuf[t + 768];
        float den = rbuf[2048 + t] + rbuf[2048 + t + 256] + rbuf[2048 + t + 512] + rbuf[2048 + t + 768];
        sh_att[t] = num / den;
    }
    __syncthreads();

    // ---- wp matvec (1024 threads, 16 rows each) ----
    float4 s4 = make_float4(0, 0, 0, 0);
#pragma unroll
    for (int i = 0; i < 16; i++) {
        int c = r * 16 + i;
        float g = sh_att[c];
        float4 a = ((const float4*)(wp + (size_t)c * C_))[u];
        s4.x = fmaf(g, a.x, s4.x); s4.y = fmaf(g, a.y, s4.y);
        s4.z = fmaf(g, a.z, s4.z); s4.w = fmaf(g, a.w, s4.w);
    }
    __syncthreads();
    red[r][u] = s4; __syncthreads();
    if (t < 256) {
        float s = 0.f;
#pragma unroll
        for (int rr = 0; rr < 16; rr++) s += ((const float*)&red[rr][t >> 2])[t & 3];
        sh_cm[t] = 1.0f / (1.0f + ex2f(-s * LOG2E));
    }
    __syncthreads();

    // ---- percentile rank (pos 25.5 -> 0.5*(s[25]+s[26])), spread ----
    {
        float cm = sh_cm[col];
        int cnt = 0;
#pragma unroll 8
        for (int j = seg * 64; j < seg * 64 + 64; j++) {
            float cj = sh_cm[j];
            cnt += (cj < cm) || (cj == cm && j < col);
        }
        ibuf[t] = cnt;
    }
    __syncthreads();
    if (t < 256) {
        int rank = ibuf[t] + ibuf[t + 256] + ibuf[t + 512] + ibuf[t + 768];
        float cm = sh_cm[t];
        if (rank == 25) sh_scal[2] = cm;
        if (rank == 26) sh_scal[3] = cm;
    }
    __syncthreads();
    if (t < 256) {
        float cm  = sh_cm[t];
        float thr = 0.5f * (sh_scal[2] + sh_scal[3]);
        float pm  = (cm > thr) ? cm : 0.f;
        float rs  = rsqrtf(bn_v[t] + EPSF) * bn_g[t];
        float a   = (1.f + cm) * rs * pm;
        float d   = (bn_b[t] - bn_m[t] * rs) * pm;
#pragma unroll
        for (int f = 0; f < 3; f++) g_wf[(b * C_ + t) * 3 + f] = a * wqkv[t * 3 + f];
        sh_d[t] = d;
    }
    __syncthreads();
    if (t < 3) {
        float cf = 0.f;
        for (int c = 0; c < C_; c++) cf = fmaf(sh_d[c], wqkv[c * 3 + t], cf);
        g_cf[b * 3 + t] = cf;
    }
}

// ---------------------------------------------------------------------------
// K4: qkv projection, 8-lane-group per pixel. grid (128, B), 256 thr.
// PDL: the 8 x-loads (the 16MB read) issue into registers BEFORE the sync,
// overlapping k_fin / k_mv.
// ---------------------------------------------------------------------------
__global__ void __launch_bounds__(256, 2) k_qkv(const float* __restrict__ x) {
    __shared__ float4 swq[64], swk[64], swv[64];
    int b = blockIdx.y, t = threadIdx.x, lane = t & 31, wid = t >> 5;
    int g8 = lane >> 3, l8 = lane & 7;
    int p = (blockIdx.x * 8 + wid) * 4 + g8;
    const float4* x4 = (const float4*)(x + (size_t)b * N_ * C_);

    cudaTriggerProgrammaticLaunchCompletion();
    // pre-sync: x loads (independent of channel pipeline)
    float4 xa[8];
#pragma unroll
    for (int j = 0; j < 8; j++) xa[j] = x4[(size_t)p * 64 + j * 8 + l8];
    cudaGridDependencySynchronize();

    // stage fused weights channel-contiguous
    {
        float a = g_wf[b * C_ * 3 + t * 3 + 0];
        float k = g_wf[b * C_ * 3 + t * 3 + 1];
        float v = g_wf[b * C_ * 3 + t * 3 + 2];
        ((float*)swq)[t] = a; ((float*)swk)[t] = k; ((float*)swv)[t] = v;
    }
    __syncthreads();

    float cf0 = g_cf[b * 3 + 0], cf1 = g_cf[b * 3 + 1], cf2 = g_cf[b * 3 + 2];

    float q = 0.f, k = 0.f, v = 0.f;
#pragma unroll
    for (int j = 0; j < 8; j++) {
        float4 a   = xa[j];
        float4 wq4 = swq[j * 8 + l8];
        float4 wk4 = swk[j * 8 + l8];
        float4 wv4 = swv[j * 8 + l8];
        q = fmaf(a.x, wq4.x, q); k = fmaf(a.x, wk4.x, k); v = fmaf(a.x, wv4.x, v);
        q = fmaf(a.y, wq4.y, q); k = fmaf(a.y, wk4.y, k); v = fmaf(a.y, wv4.y, v);
        q = fmaf(a.z, wq4.z, q); k = fmaf(a.z, wk4.z, k); v = fmaf(a.z, wv4.z, v);
        q = fmaf(a.w, wq4.w, q); k = fmaf(a.w, wk4.w, k); v = fmaf(a.w, wv4.w, v);
    }
#pragma unroll
    for (int o = 4; o > 0; o >>= 1) {
        q += __shfl_xor_sync(0xffffffffu, q, o);
        k += __shfl_xor_sync(0xffffffffu, k, o);
        v += __shfl_xor_sync(0xffffffffu, v, o);
    }
    float kk = k + cf1;
    if (l8 == 0) {
        g_qs[b * N_ + p] = q + cf0;
        g_ks[b * N_ + p] = kk;
        g_vs[b * N_ + p] = v + cf2;
    }
    float lmax = kk, lmin = kk;
#pragma unroll
    for (int o = 16; o > 0; o >>= 1) {
        lmax = fmaxf(lmax, __shfl_xor_sync(0xffffffffu, lmax, o));
        lmin = fminf(lmin, __shfl_xor_sync(0xffffffffu, lmin, o));
    }
    if (lane == 0) {
        atomicMax(&g_kmax_u[b], encf(lmax));
        atomicMin(&g_kmin_u[b], encf(lmin));
    }
}

// ---------------------------------------------------------------------------
// K5: spatial softmax attention. grid (111, B) = 444 blocks (single wave,
// 3/SM). Warps 0-4: 5 rows, warps 5-7: 4 rows (37/blk).
// ---------------------------------------------------------------------------
template <int NR>
__device__ __forceinline__ void attn_rows(const float4* skv4, int lane, int b, int i0,
                                          float kmx, float kmn, float* __restrict__ out) {
    float c1[NR], mb[NR], num[NR], den[NR], num2[NR], den2[NR];
#pragma unroll
    for (int s = 0; s < NR; s++) {
        int i = i0 + s;
        float qi = g_qs[b * N_ + ((i < N_) ? i : (N_ - 1))];
        float m  = (qi >= 0.f) ? qi * kmx : qi * kmn;
        c1[s] = qi * LOG2E; mb[s] = m * LOG2E;
        num[s] = 0.f; den[s] = 0.f; num2[s] = 0.f; den2[s] = 0.f;
    }
#pragma unroll 2
    for (int p = lane; p < N_ / 2; p += 32) {
        float4 kv = skv4[p];
#pragma unroll
        for (int s = 0; s < NR; s++) {
            float e0 = ex2f(fmaf(c1[s], kv.x, -mb[s]));
            den[s] += e0;
            num[s] = fmaf(e0, kv.y, num[s]);
            float e1 = ex2f(fmaf(c1[s], kv.z, -mb[s]));
            den2[s] += e1;
            num2[s] = fmaf(e1, kv.w, num2[s]);
        }
    }
#pragma unroll
    for (int s = 0; s < NR; s++) {
        float n = num[s] + num2[s], d = den[s] + den2[s];
#pragma unroll
        for (int o = 16; o > 0; o >>= 1) {
            n += __shfl_xor_sync(0xffffffffu, n, o);
            d += __shfl_xor_sync(0xffffffffu, d, o);
        }
        int i = i0 + s;
        if (lane == 0 && i < N_) out[b * N_ + i] = g_vs[b * N_ + i] + n / d;
    }
}

__global__ void __launch_bounds__(256) k_attn(float* __restrict__ out) {
    cudaGridDependencySynchronize();
    __shared__ float4 skv4[N_ / 2];
    int b = blockIdx.y, t = threadIdx.x, lane = t & 31, wid = t >> 5;

    const float2* kp = (const float2*)(g_ks + b * N_);
    const float2* vp = (const float2*)(g_vs + b * N_);
    for (int p = t; p < N_ / 2; p += 256) {
        float2 k2 = kp[p], v2 = vp[p];
        skv4[p] = make_float4(k2.x, v2.x, k2.y, v2.y);
    }
    __syncthreads();

    float kmx = decf(g_kmax_u[b]), kmn = decf(g_kmin_u[b]);
    int base = blockIdx.x * ARPB;

    if (wid < 5)
        attn_rows<5>(skv4, lane, b, base + wid * 5, kmx, kmn, out);
    else
        attn_rows<4>(skv4, lane, b, base + 25 + (wid - 5) * 4, kmx, kmn, out);
}

// ---------------------------------------------------------------------------
extern "C" void kernel_launch(void* const* d_in, const int* in_sizes, int n_in,
                              void* d_out, int out_size) {
    const float* x    = (const float*)d_in[0];
    const float* ca_g = (const float*)d_in[1];
    const float* ca_b = (const float*)d_in[2];
    const float* ca_m = (const float*)d_in[3];
    const float* ca_v = (const float*)d_in[4];
    const float* wq   = (const float*)d_in[5];
    const float* wk   = (const float*)d_in[6];
    const float* wv   = (const float*)d_in[7];
    const float* wp   = (const float*)d_in[8];
    const float* bn_g = (const float*)d_in[9];
    const float* bn_b = (const float*)d_in[10];
    const float* bn_m = (const float*)d_in[11];
    const float* bn_v = (const float*)d_in[12];
    const float* wqkv = (const float*)d_in[13];
    float* out = (float*)d_out;

    cudaLaunchAttribute pdl[1];
    pdl[0].id = cudaLaunchAttributeProgrammaticStreamSerialization;
    pdl[0].val.programmaticStreamSerializationAllowed = 1;

    k_gap<<<dim3(GCH, B_), 256>>>(x, wq, wk, wv, wp);

    {
        cudaLaunchConfig_t cfg = {};
        cfg.gridDim = dim3(16, B_); cfg.blockDim = dim3(256);
        cfg.attrs = pdl; cfg.numAttrs = 1;
        cudaLaunchKernelEx(&cfg, k_mv, ca_g, ca_b, ca_m, ca_v, wq, wk, wv);
    }
    {
        cudaLaunchConfig_t cfg = {};
        cfg.gridDim = dim3(B_); cfg.blockDim = dim3(1024);
        cfg.attrs = pdl; cfg.numAttrs = 1;
        cudaLaunchKernelEx(&cfg, k_fin, wp, bn_g, bn_b, bn_m, bn_v, wqkv);
    }
    {
        cudaLaunchConfig_t cfg = {};
        cfg.gridDim = dim3(128, B_); cfg.blockDim = dim3(256);
        cfg.attrs = pdl; cfg.numAttrs = 1;
        cudaLaunchKernelEx(&cfg, k_qkv, x);
    }
    {
        cudaLaunchConfig_t cfg = {};
        cfg.gridDim = dim3(ABL, B_); cfg.blockDim = dim3(256);
        cfg.attrs = pdl; cfg.numAttrs = 1;
        cudaLaunchKernelEx(&cfg, k_attn, out);
    }
}

// round 13
// speedup vs baseline: 1.0963x; 1.0963x over previous
#include <cuda_runtime.h>

#define C_    256
#define B_    4
#define N_    4096
#define EPSF  1e-3f
#define LOG2E 1.4426950408889634f
#define GCH   128    // gap partial chunks per batch
#define ABL   111    // attention blocks per batch (111*37 >= 4096, 444 = 148*3)
#define ARPB  37     // attention rows per block

typedef unsigned long long u64;

// ---- scratch (device globals, no allocations) ----
__device__ float g_partial[B_ * GCH * C_];
__device__ float g_mv[B_ * 16 * 3 * C_];    // matvec partials [b][seg][m][c]
__device__ float g_wf[B_ * C_ * 3];
__device__ float g_cf[B_ * 3];
__device__ float g_qs[B_ * N_];
__device__ float g_ks[B_ * N_];
__device__ float g_vs[B_ * N_];
__device__ unsigned g_kmax_u[B_];
__device__ unsigned g_kmin_u[B_];

__device__ __forceinline__ float ex2f(float x) {
    float r;
    asm("ex2.approx.ftz.f32 %0, %1;" : "=f"(r) : "f"(x));
    return r;
}
__device__ __forceinline__ unsigned encf(float f) {
    unsigned u = __float_as_uint(f);
    return (u & 0x80000000u) ? ~u : (u | 0x80000000u);
}
__device__ __forceinline__ float decf(unsigned u) {
    return __uint_as_float((u & 0x80000000u) ? (u ^ 0x80000000u) : ~u);
}
__device__ __forceinline__ void l2_prefetch(const void* p) {
    asm volatile("prefetch.global.L2 [%0];" :: "l"(p));
}

// ---- packed f32x2 helpers (FFMA2 path: PTX-only) ----
__device__ __forceinline__ u64 pack2(float lo, float hi) {
    u64 d; asm("mov.b64 %0, {%1, %2};" : "=l"(d) : "f"(lo), "f"(hi)); return d;
}
__device__ __forceinline__ void unpack2(u64 a, float& lo, float& hi) {
    asm("mov.b64 {%0, %1}, %2;" : "=f"(lo), "=f"(hi) : "l"(a));
}
__device__ __forceinline__ u64 fma2_(u64 a, u64 b, u64 c) {
    u64 d; asm("fma.rn.f32x2 %0, %1, %2, %3;" : "=l"(d) : "l"(a), "l"(b), "l"(c)); return d;
}
__device__ __forceinline__ u64 add2_(u64 a, u64 b) {
    u64 d; asm("add.rn.f32x2 %0, %1, %2;" : "=l"(d) : "l"(a), "l"(b)); return d;
}

// ---------------------------------------------------------------------------
// K1: GAP partials. grid (GCH, B), 256 thr. Prefetches weights into L2.
// ---------------------------------------------------------------------------
__global__ void k_gap(const float* __restrict__ x,
                      const float* __restrict__ wq, const float* __restrict__ wk,
                      const float* __restrict__ wv, const float* __restrict__ wp) {
    __shared__ float4 sh[4][64];
    int b = blockIdx.y, blk = blockIdx.x, t = threadIdx.x;
    if (blk == 0 && b == 0 && t < B_) {
        g_kmax_u[t] = 0u;
        g_kmin_u[t] = 0xffffffffu;
    }
    if (t < 16) {
        int g = b * GCH + blk;
        int line = g * 4 + (t & 3);
        const float* base = (t >> 2) == 0 ? wq : (t >> 2) == 1 ? wk : (t >> 2) == 2 ? wv : wp;
        l2_prefetch(base + line * 32);
    }
    int c4 = t & 63, rs = t >> 6;
    const float4* xp = (const float4*)(x + (size_t)b * N_ * C_);
    float4 s = make_float4(0.f, 0.f, 0.f, 0.f);
#pragma unroll
    for (int i = 0; i < 8; i++) {
        int row = blk * 32 + rs + 4 * i;
        float4 a = xp[(size_t)row * 64 + c4];
        s.x += a.x; s.y += a.y; s.z += a.z; s.w += a.w;
    }
    sh[rs][c4] = s;
    __syncthreads();
    if (t < 64) {
        float4 a = sh[0][t], bb = sh[1][t], c = sh[2][t], d = sh[3][t];
        float4 r;
        r.x = a.x + bb.x + c.x + d.x;
        r.y = a.y + bb.y + c.y + d.y;
        r.z = a.z + bb.z + c.z + d.z;
        r.w = a.w + bb.w + c.w + d.w;
        ((float4*)(g_partial + (size_t)(b * GCH + blk) * C_))[t] = r;
    }
}

// ---------------------------------------------------------------------------
// K2: gap-final + BN + q/k/v matvec PARTIALS. grid (16, B), 256 thr.
// ---------------------------------------------------------------------------
__global__ void __launch_bounds__(256) k_mv(
        const float* __restrict__ ca_g, const float* __restrict__ ca_b,
        const float* __restrict__ ca_m, const float* __restrict__ ca_v,
        const float* __restrict__ wq,   const float* __restrict__ wk,
        const float* __restrict__ wv) {
    __shared__ float4 red[4][65];
    __shared__ float sh_gn[16];
    int seg = blockIdx.x, b = blockIdx.y, t = threadIdx.x;
    int u = t & 63, r2 = t >> 6;
    float* rb = (float*)red;

    {
        int c_l = t >> 4, piece = t & 15;
        float s = 0.f;
#pragma unroll
        for (int j = 0; j < 8; j++)
            s += g_partial[(size_t)(b * GCH + piece * 8 + j) * C_ + seg * 16 + c_l];
        rb[c_l * 16 + piece] = s;
    }
    __syncthreads();
    if (t < 16) {
        float ss = 0.f;
#pragma unroll
        for (int p = 0; p < 16; p++) ss += rb[t * 16 + p];
        float gap = ss * (1.f / N_);
        int c = seg * 16 + t;
        sh_gn[t] = (gap - ca_m[c]) * rsqrtf(ca_v[c] + EPSF) * ca_g[c] + ca_b[c];
    }
    __syncthreads();

    float4 q4 = make_float4(0, 0, 0, 0), k4 = q4, v4 = q4;
#pragma unroll
    for (int i = 0; i < 4; i++) {
        int cl = r2 * 4 + i;
        int c  = seg * 16 + cl;
        float gg = sh_gn[cl];
        float4 a = ((const float4*)(wq + (size_t)c * C_))[u];
        q4.x = fmaf(gg, a.x, q4.x); q4.y = fmaf(gg, a.y, q4.y);
        q4.z = fmaf(gg, a.z, q4.z); q4.w = fmaf(gg, a.w, q4.w);
        float4 bb = ((const float4*)(wk + (size_t)c * C_))[u];
        k4.x = fmaf(gg, bb.x, k4.x); k4.y = fmaf(gg, bb.y, k4.y);
        k4.z = fmaf(gg, bb.z, k4.z); k4.w = fmaf(gg, bb.w, k4.w);
        float4 cc = ((const float4*)(wv + (size_t)c * C_))[u];
        v4.x = fmaf(gg, cc.x, v4.x); v4.y = fmaf(gg, cc.y, v4.y);
        v4.z = fmaf(gg, cc.z, v4.z); v4.w = fmaf(gg, cc.w, v4.w);
    }
    float* mv = g_mv + (size_t)(b * 16 + seg) * 3 * C_;
    __syncthreads();
    red[r2][u] = q4; __syncthreads();
    if (t < 64) {
        float4 a = red[0][t], bb = red[1][t], c = red[2][t], d = red[3][t];
        ((float4*)mv)[t] = make_float4(a.x + bb.x + c.x + d.x, a.y + bb.y + c.y + d.y,
                                       a.z + bb.z + c.z + d.z, a.w + bb.w + c.w + d.w);
    }
    __syncthreads();
    red[r2][u] = k4; __syncthreads();
    if (t < 64) {
        float4 a = red[0][t], bb = red[1][t], c = red[2][t], d = red[3][t];
        ((float4*)(mv + C_))[t] = make_float4(a.x + bb.x + c.x + d.x, a.y + bb.y + c.y + d.y,
                                              a.z + bb.z + c.z + d.z, a.w + bb.w + c.w + d.w);
    }
    __syncthreads();
    red[r2][u] = v4; __syncthreads();
    if (t < 64) {
        float4 a = red[0][t], bb = red[1][t], c = red[2][t], d = red[3][t];
        ((float4*)(mv + 2 * C_))[t] = make_float4(a.x + bb.x + c.x + d.x, a.y + bb.y + c.y + d.y,
                                                  a.z + bb.z + c.z + d.z, a.w + bb.w + c.w + d.w);
    }
}

// ---------------------------------------------------------------------------
// K3: finalize channel attention. grid B, 1024 thr.
// ---------------------------------------------------------------------------
__global__ void __launch_bounds__(1024) k_fin(
        const float* __restrict__ wp,
        const float* __restrict__ bn_g, const float* __restrict__ bn_b,
        const float* __restrict__ bn_m, const float* __restrict__ bn_v,
        const float* __restrict__ wqkv) {
    __shared__ float4 red[16][65];
    __shared__ float sh_q[C_], sh_k[C_], sh_v[C_];
    __shared__ float sh_att[C_], sh_cm[C_], sh_d[C_];
    __shared__ float sh_mx[8], sh_mn[8], sh_scal[4];
    float* rbuf = (float*)red;
    int*   ibuf = (int*)red;
    int b = blockIdx.x, t = threadIdx.x;
    int lane = t & 31, wid = t >> 5;
    int col = t & 255, seg = t >> 8;
    int u = t & 63, r = t >> 6;

    {
        float qf = 0.f, kf = 0.f, vf = 0.f;
#pragma unroll
        for (int s2 = 0; s2 < 4; s2++) {
            const float* mv = g_mv + (size_t)(b * 16 + seg * 4 + s2) * 3 * C_;
            qf += mv[col]; kf += mv[C_ + col]; vf += mv[2 * C_ + col];
        }
        rbuf[t] = qf; rbuf[1024 + t] = kf; rbuf[2048 + t] = vf;
    }
    __syncthreads();
    if (t < 256) {
        sh_q[t] = rbuf[t] + rbuf[t + 256] + rbuf[t + 512] + rbuf[t + 768];
        sh_k[t] = rbuf[1024 + t] + rbuf[1024 + t + 256] + rbuf[1024 + t + 512] + rbuf[1024 + t + 768];
        sh_v[t] = rbuf[2048 + t] + rbuf[2048 + t + 256] + rbuf[2048 + t + 512] + rbuf[2048 + t + 768];
    }
    __syncthreads();

    if (t < 256) {
        float kk = sh_k[t];
        float mx = kk, mn = kk;
#pragma unroll
        for (int o = 16; o > 0; o >>= 1) {
            mx = fmaxf(mx, __shfl_xor_sync(0xffffffffu, mx, o));
            mn = fminf(mn, __shfl_xor_sync(0xffffffffu, mn, o));
        }
        if (lane == 0) { sh_mx[wid] = mx; sh_mn[wid] = mn; }
    }
    __syncthreads();
    if (t == 0) {
        float mx = sh_mx[0], mn = sh_mn[0];
        for (int i = 1; i < 8; i++) { mx = fmaxf(mx, sh_mx[i]); mn = fminf(mn, sh_mn[i]); }
        sh_scal[0] = mx; sh_scal[1] = mn;
    }
    __syncthreads();

    {
        float q = sh_q[col];
        float m = (q >= 0.f) ? q * sh_scal[0] : q * sh_scal[1];
        float c1 = q * LOG2E, mb = m * LOG2E;
        float num = 0.f, den = 0.f;
#pragma unroll 8
        for (int j = seg * 64; j < seg * 64 + 64; j++) {
            float e = ex2f(fmaf(c1, sh_k[j], -mb));
            den += e;
            num = fmaf(e, sh_v[j], num);
        }
        rbuf[t] = num; rbuf[2048 + t] = den;
    }
    __syncthreads();
    if (t < 256) {
        float num = rbuf[t] + rbuf[t + 256] + rbuf[t + 512] + rbuf[t + 768];
        float den = rbuf[2048 + t] + rbuf[2048 + t + 256] + rbuf[2048 + t + 512] + rbuf[2048 + t + 768];
        sh_att[t] = num / den;
    }
    __syncthreads();

    float4 s4 = make_float4(0, 0, 0, 0);
#pragma unroll
    for (int i = 0; i < 16; i++) {
        int c = r * 16 + i;
        float g = sh_att[c];
        float4 a = ((const float4*)(wp + (size_t)c * C_))[u];
        s4.x = fmaf(g, a.x, s4.x); s4.y = fmaf(g, a.y, s4.y);
        s4.z = fmaf(g, a.z, s4.z); s4.w = fmaf(g, a.w, s4.w);
    }
    __syncthreads();
    red[r][u] = s4; __syncthreads();
    if (t < 256) {
        float s = 0.f;
#pragma unroll
        for (int rr = 0; rr < 16; rr++) s += ((const float*)&red[rr][t >> 2])[t & 3];
        sh_cm[t] = 1.0f / (1.0f + ex2f(-s * LOG2E));
    }
    __syncthreads();

    {
        float cm = sh_cm[col];
        int cnt = 0;
#pragma unroll 8
        for (int j = seg * 64; j < seg * 64 + 64; j++) {
            float cj = sh_cm[j];
            cnt += (cj < cm) || (cj == cm && j < col);
        }
        ibuf[t] = cnt;
    }
    __syncthreads();
    if (t < 256) {
        int rank = ibuf[t] + ibuf[t + 256] + ibuf[t + 512] + ibuf[t + 768];
        float cm = sh_cm[t];
        if (rank == 25) sh_scal[2] = cm;
        if (rank == 26) sh_scal[3] = cm;
    }
    __syncthreads();
    if (t < 256) {
        float cm  = sh_cm[t];
        float thr = 0.5f * (sh_scal[2] + sh_scal[3]);
        float pm  = (cm > thr) ? cm : 0.f;
        float rs  = rsqrtf(bn_v[t] + EPSF) * bn_g[t];
        float a   = (1.f + cm) * rs * pm;
        float d   = (bn_b[t] - bn_m[t] * rs) * pm;
#pragma unroll
        for (int f = 0; f < 3; f++) g_wf[(b * C_ + t) * 3 + f] = a * wqkv[t * 3 + f];
        sh_d[t] = d;
    }
    __syncthreads();
    if (t < 3) {
        float cf = 0.f;
        for (int c = 0; c < C_; c++) cf = fmaf(sh_d[c], wqkv[c * 3 + t], cf);
        g_cf[b * 3 + t] = cf;
    }
}

// ---------------------------------------------------------------------------
// K4: qkv projection, 8-lane-group per pixel. grid (128, B), 256 thr.
// ---------------------------------------------------------------------------
__global__ void __launch_bounds__(256, 4) k_qkv(const float* __restrict__ x) {
    __shared__ float4 swq[64], swk[64], swv[64];
    int b = blockIdx.y, t = threadIdx.x, lane = t & 31, wid = t >> 5;

    {
        float a = g_wf[b * C_ * 3 + t * 3 + 0];
        float k = g_wf[b * C_ * 3 + t * 3 + 1];
        float v = g_wf[b * C_ * 3 + t * 3 + 2];
        ((float*)swq)[t] = a; ((float*)swk)[t] = k; ((float*)swv)[t] = v;
    }
    __syncthreads();

    float cf0 = g_cf[b * 3 + 0], cf1 = g_cf[b * 3 + 1], cf2 = g_cf[b * 3 + 2];

    int g8 = lane >> 3, l8 = lane & 7;
    int p = (blockIdx.x * 8 + wid) * 4 + g8;
    const float4* x4 = (const float4*)(x + (size_t)b * N_ * C_);

    float q = 0.f, k = 0.f, v = 0.f;
#pragma unroll
    for (int j = 0; j < 8; j++) {
        float4 a  = x4[(size_t)p * 64 + j * 8 + l8];
        float4 wq4 = swq[j * 8 + l8];
        float4 wk4 = swk[j * 8 + l8];
        float4 wv4 = swv[j * 8 + l8];
        q = fmaf(a.x, wq4.x, q); k = fmaf(a.x, wk4.x, k); v = fmaf(a.x, wv4.x, v);
        q = fmaf(a.y, wq4.y, q); k = fmaf(a.y, wk4.y, k); v = fmaf(a.y, wv4.y, v);
        q = fmaf(a.z, wq4.z, q); k = fmaf(a.z, wk4.z, k); v = fmaf(a.z, wv4.z, v);
        q = fmaf(a.w, wq4.w, q); k = fmaf(a.w, wk4.w, k); v = fmaf(a.w, wv4.w, v);
    }
#pragma unroll
    for (int o = 4; o > 0; o >>= 1) {
        q += __shfl_xor_sync(0xffffffffu, q, o);
        k += __shfl_xor_sync(0xffffffffu, k, o);
        v += __shfl_xor_sync(0xffffffffu, v, o);
    }
    float kk = k + cf1;
    if (l8 == 0) {
        g_qs[b * N_ + p] = q + cf0;
        g_ks[b * N_ + p] = kk;
        g_vs[b * N_ + p] = v + cf2;
    }
    float lmax = kk, lmin = kk;
#pragma unroll
    for (int o = 16; o > 0; o >>= 1) {
        lmax = fmaxf(lmax, __shfl_xor_sync(0xffffffffu, lmax, o));
        lmin = fminf(lmin, __shfl_xor_sync(0xffffffffu, lmin, o));
    }
    if (lane == 0) {
        atomicMax(&g_kmax_u[b], encf(lmax));
        atomicMin(&g_kmin_u[b], encf(lmin));
    }
}

// ---------------------------------------------------------------------------
// K5: spatial softmax attention, mixed MUFU + packed-poly exp2.
// grid (111, B) = 444 blocks (single wave, 3/SM). Warps 0-4: 5 rows,
// warps 5-7: 4 rows. k/v in smem as packed f32x2 pairs (LDS.64 operands).
// Every 3rd k-pair iteration is evaluated with an FMA-pipe f32x2 polynomial,
// offloading the MUFU bottleneck. Rows with exponent range beyond poly
// safety fall back to all-MUFU (warp-uniform, analytic bound).
// ---------------------------------------------------------------------------
template <int NR>
__device__ __forceinline__ void attn_rows(const u64* sk2, const u64* sv2, int lane,
                                          int b, int i0, float kmx, float kmn,
                                          float* __restrict__ out) {
    u64 c1_2[NR], nmb2[NR], den2[NR], num2[NR];
    bool bad = false;
#pragma unroll
    for (int s = 0; s < NR; s++) {
        int i = i0 + s;
        float qi = g_qs[b * N_ + ((i < N_) ? i : (N_ - 1))];
        float c1 = qi * LOG2E;
        float mb = fmaxf(c1 * kmx, c1 * kmn);
        if (fminf(c1 * kmx, c1 * kmn) - mb < -120.f) bad = true;
        c1_2[s] = pack2(c1, c1);
        nmb2[s] = pack2(-mb, -mb);
        den2[s] = 0ull; num2[s] = 0ull;
    }
    const u64 RND2 = pack2(12582912.f, 12582912.f);
    const u64 NEG1 = pack2(-1.f, -1.f);
    const u64 P5 = pack2(1.3333558e-3f, 1.3333558e-3f);
    const u64 P4 = pack2(9.6181291e-3f, 9.6181291e-3f);
    const u64 P3 = pack2(5.5504109e-2f, 5.5504109e-2f);
    const u64 P2 = pack2(2.4022651e-1f, 2.4022651e-1f);
    const u64 P1 = pack2(6.9314718e-1f, 6.9314718e-1f);
    const u64 ONE2 = pack2(1.f, 1.f);

    auto mufu_it = [&](int p) {
        u64 k2 = sk2[p], v2 = sv2[p];
#pragma unroll
        for (int s = 0; s < NR; s++) {
            u64 arg = fma2_(c1_2[s], k2, nmb2[s]);
            float a0, a1; unpack2(arg, a0, a1);
            u64 e2 = pack2(ex2f(a0), ex2f(a1));
            den2[s] = add2_(den2[s], e2);
            num2[s] = fma2_(e2, v2, num2[s]);
        }
    };
    auto poly_it = [&](int p) {
        u64 k2 = sk2[p], v2 = sv2[p];
#pragma unroll
        for (int s = 0; s < NR; s++) {
            u64 arg = fma2_(c1_2[s], k2, nmb2[s]);
            u64 z   = add2_(arg, RND2);
            u64 zi  = fma2_(RND2, NEG1, z);      // z - RND (rounded integer part)
            u64 fr  = fma2_(zi, NEG1, arg);      // arg - zi, in [-0.5, 0.5]
            u64 pl  = fma2_(fr, P5, P4);
            pl = fma2_(fr, pl, P3);
            pl = fma2_(fr, pl, P2);
            pl = fma2_(fr, pl, P1);
            pl = fma2_(fr, pl, ONE2);
            float zl, zh, pll, plh;
            unpack2(z, zl, zh);
            unpack2(pl, pll, plh);
            float e_lo = __uint_as_float(__float_as_uint(pll) + (__float_as_uint(zl) << 23));
            float e_hi = __uint_as_float(__float_as_uint(plh) + (__float_as_uint(zh) << 23));
            u64 e2 = pack2(e_lo, e_hi);
            den2[s] = add2_(den2[s], e2);
            num2[s] = fma2_(e2, v2, num2[s]);
        }
    };

    if (!bad) {
        int p = lane;
#pragma unroll 1
        for (int g = 0; g < 21; g++) {
            mufu_it(p); mufu_it(p + 32); poly_it(p + 64);
            p += 96;
        }
        mufu_it(p);                              // iteration 63
    } else {
#pragma unroll 1
        for (int p = lane; p < N_ / 2; p += 32) mufu_it(p);
    }

#pragma unroll
    for (int s = 0; s < NR; s++) {
        float d0, d1, n0, n1;
        unpack2(den2[s], d0, d1);
        unpack2(num2[s], n0, n1);
        float d = d0 + d1, n = n0 + n1;
#pragma unroll
        for (int o = 16; o > 0; o >>= 1) {
            n += __shfl_xor_sync(0xffffffffu, n, o);
            d += __shfl_xor_sync(0xffffffffu, d, o);
        }
        int i = i0 + s;
        if (lane == 0 && i < N_) out[b * N_ + i] = g_vs[b * N_ + i] + n / d;
    }
}

__global__ void __launch_bounds__(256) k_attn(float* __restrict__ out) {
    __shared__ u64 sk2[N_ / 2];
    __shared__ u64 sv2[N_ / 2];
    int b = blockIdx.y, t = threadIdx.x, lane = t & 31, wid = t >> 5;

    const u64* kp = (const u64*)(g_ks + b * N_);
    const u64* vp = (const u64*)(g_vs + b * N_);
    for (int p = t; p < N_ / 2; p += 256) { sk2[p] = kp[p]; sv2[p] = vp[p]; }
    __syncthreads();

    float kmx = decf(g_kmax_u[b]), kmn = decf(g_kmin_u[b]);
    int base = blockIdx.x * ARPB;

    if (wid < 5)
        attn_rows<5>(sk2, sv2, lane, b, base + wid * 5, kmx, kmn, out);
    else
        attn_rows<4>(sk2, sv2, lane, b, base + 25 + (wid - 5) * 4, kmx, kmn, out);
}

// ---------------------------------------------------------------------------
extern "C" void kernel_launch(void* const* d_in, const int* in_sizes, int n_in,
                              void* d_out, int out_size) {
    const float* x    = (const float*)d_in[0];
    const float* ca_g = (const float*)d_in[1];
    const float* ca_b = (const float*)d_in[2];
    const float* ca_m = (const float*)d_in[3];
    const float* ca_v = (const float*)d_in[4];
    const float* wq   = (const float*)d_in[5];
    const float* wk   = (const float*)d_in[6];
    const float* wv   = (const float*)d_in[7];
    const float* wp   = (const float*)d_in[8];
    const float* bn_g = (const float*)d_in[9];
    const float* bn_b = (const float*)d_in[10];
    const float* bn_m = (const float*)d_in[11];
    const float* bn_v = (const float*)d_in[12];
    const float* wqkv = (const float*)d_in[13];
    float* out = (float*)d_out;

    k_gap<<<dim3(GCH, B_), 256>>>(x, wq, wk, wv, wp);
    k_mv<<<dim3(16, B_), 256>>>(ca_g, ca_b, ca_m, ca_v, wq, wk, wv);
    k_fin<<<B_, 1024>>>(wp, bn_g, bn_b, bn_m, bn_v, wqkv);
    k_qkv<<<dim3(128, B_), 256>>>(x);
    k_attn<<<dim3(ABL, B_), 256>>>(out);
}

// round 14
// speedup vs baseline: 1.1514x; 1.0502x over previous
#include <cuda_runtime.h>

#define C_    256
#define B_    4
#define N_    4096
#define EPSF  1e-3f
#define LOG2E 1.4426950408889634f
#define GCH   128    // gap partial chunks per batch
#define ABL   111    // attention blocks per batch (111*37 >= 4096, 444 = 148*3)
#define ARPB  37     // attention rows per block

// ---- scratch (device globals, no allocations) ----
__device__ float g_partial[B_ * GCH * C_];
__device__ float g_mv[B_ * 8 * 3 * C_];     // matvec partials [b][seg][m][c]
__device__ float g_wpp[B_ * 8 * C_];        // wp matvec partials
__device__ float g_wf[B_ * C_ * 3];
__device__ float g_cf[B_ * 3];
__device__ float g_qs[B_ * N_];
__device__ float g_ks[B_ * N_];
__device__ float g_vs[B_ * N_];
__device__ unsigned g_kmax_u[B_];
__device__ unsigned g_kmin_u[B_];

__device__ __forceinline__ float ex2f(float x) {
    float r;
    asm("ex2.approx.ftz.f32 %0, %1;" : "=f"(r) : "f"(x));
    return r;
}
__device__ __forceinline__ unsigned encf(float f) {
    unsigned u = __float_as_uint(f);
    return (u & 0x80000000u) ? ~u : (u | 0x80000000u);
}
__device__ __forceinline__ float decf(unsigned u) {
    return __uint_as_float((u & 0x80000000u) ? (u ^ 0x80000000u) : ~u);
}
__device__ __forceinline__ void l2_prefetch(const void* p) {
    asm volatile("prefetch.global.L2 [%0];" :: "l"(p));
}
__device__ __forceinline__ void cluster_sync_() {
    asm volatile("barrier.cluster.arrive.aligned;" ::: "memory");
    asm volatile("barrier.cluster.wait.aligned;" ::: "memory");
}

// ---------------------------------------------------------------------------
// K1: GAP partials. grid (GCH, B), 256 thr. Prefetches weights into L2.
// ---------------------------------------------------------------------------
__global__ void k_gap(const float* __restrict__ x,
                      const float* __restrict__ wq, const float* __restrict__ wk,
                      const float* __restrict__ wv, const float* __restrict__ wp) {
    __shared__ float4 sh[4][64];
    int b = blockIdx.y, blk = blockIdx.x, t = threadIdx.x;
    if (blk == 0 && b == 0 && t < B_) {
        g_kmax_u[t] = 0u;
        g_kmin_u[t] = 0xffffffffu;
    }
    if (t < 16) {
        int g = b * GCH + blk;
        int line = g * 4 + (t & 3);
        const float* base = (t >> 2) == 0 ? wq : (t >> 2) == 1 ? wk : (t >> 2) == 2 ? wv : wp;
        l2_prefetch(base + line * 32);
    }
    int c4 = t & 63, rs = t >> 6;
    const float4* xp = (const float4*)(x + (size_t)b * N_ * C_);
    float4 s = make_float4(0.f, 0.f, 0.f, 0.f);
#pragma unroll
    for (int i = 0; i < 8; i++) {
        int row = blk * 32 + rs + 4 * i;
        float4 a = xp[(size_t)row * 64 + c4];
        s.x += a.x; s.y += a.y; s.z += a.z; s.w += a.w;
    }
    sh[rs][c4] = s;
    __syncthreads();
    if (t < 64) {
        float4 a = sh[0][t], bb = sh[1][t], c = sh[2][t], d = sh[3][t];
        float4 r;
        r.x = a.x + bb.x + c.x + d.x;
        r.y = a.y + bb.y + c.y + d.y;
        r.z = a.z + bb.z + c.z + d.z;
        r.w = a.w + bb.w + c.w + d.w;
        ((float4*)(g_partial + (size_t)(b * GCH + blk) * C_))[t] = r;
    }
}

// ---------------------------------------------------------------------------
// K2: merged channel pipeline, cluster (8,1,1). grid (8, B), 256 thr.
// Block seg owns channels [seg*32, +32).
//  A: gap-final + BN + q/k/v matvec partials -> g_mv
//  cluster.sync
//  B: reduce partials (all blocks), k min/max, channel softmax for own 32
//     rows, wp matvec partial -> g_wpp
//  cluster.sync
//  C: rank-0 block: sigmoid + percentile + fused-weight finalize
// ---------------------------------------------------------------------------
__global__ void __cluster_dims__(8, 1, 1) __launch_bounds__(256) k_ch(
        const float* __restrict__ ca_g, const float* __restrict__ ca_b,
        const float* __restrict__ ca_m, const float* __restrict__ ca_v,
        const float* __restrict__ wq,   const float* __restrict__ wk,
        const float* __restrict__ wv,   const float* __restrict__ wp,
        const float* __restrict__ bn_g, const float* __restrict__ bn_b,
        const float* __restrict__ bn_m, const float* __restrict__ bn_v,
        const float* __restrict__ wqkv) {
    __shared__ float4 red[4][65];
    __shared__ float sh_gn[32], sh_att[32];
    __shared__ float sh_q[C_], sh_k[C_], sh_v[C_];
    __shared__ float sh_cm[C_], sh_d[C_];
    __shared__ float sh_mx[8], sh_mn[8], sh_scal[4];
    int seg = blockIdx.x, b = blockIdx.y, t = threadIdx.x;
    int lane = t & 31, wid = t >> 5;
    int u = t & 63, r2 = t >> 6;
    float* rb = (float*)red;

    // ---- A1: gap final for this block's 32 channels ----
    {
        int c_l = t >> 3, piece = t & 7;
        float s = 0.f;
#pragma unroll
        for (int j = 0; j < 16; j++)
            s += g_partial[(size_t)(b * GCH + piece * 16 + j) * C_ + seg * 32 + c_l];
        rb[c_l * 8 + piece] = s;
    }
    __syncthreads();
    if (t < 32) {
        float ss = 0.f;
#pragma unroll
        for (int p = 0; p < 8; p++) ss += rb[t * 8 + p];
        float gap = ss * (1.f / N_);
        int c = seg * 32 + t;
        sh_gn[t] = (gap - ca_m[c]) * rsqrtf(ca_v[c] + EPSF) * ca_g[c] + ca_b[c];
    }
    __syncthreads();

    // ---- A2: q/k/v matvec partials over 32 channel-rows ----
    float4 q4 = make_float4(0, 0, 0, 0), k4 = q4, v4 = q4;
#pragma unroll
    for (int i = 0; i < 8; i++) {
        int cl = r2 * 8 + i;
        int c  = seg * 32 + cl;
        float gg = sh_gn[cl];
        float4 a = ((const float4*)(wq + (size_t)c * C_))[u];
        q4.x = fmaf(gg, a.x, q4.x); q4.y = fmaf(gg, a.y, q4.y);
        q4.z = fmaf(gg, a.z, q4.z); q4.w = fmaf(gg, a.w, q4.w);
        float4 bb = ((const float4*)(wk + (size_t)c * C_))[u];
        k4.x = fmaf(gg, bb.x, k4.x); k4.y = fmaf(gg, bb.y, k4.y);
        k4.z = fmaf(gg, bb.z, k4.z); k4.w = fmaf(gg, bb.w, k4.w);
        float4 cc = ((const float4*)(wv + (size_t)c * C_))[u];
        v4.x = fmaf(gg, cc.x, v4.x); v4.y = fmaf(gg, cc.y, v4.y);
        v4.z = fmaf(gg, cc.z, v4.z); v4.w = fmaf(gg, cc.w, v4.w);
    }
    float* mv = g_mv + (size_t)(b * 8 + seg) * 3 * C_;
    __syncthreads();
    red[r2][u] = q4; __syncthreads();
    if (t < 64) {
        float4 a = red[0][t], bb = red[1][t], c = red[2][t], d = red[3][t];
        ((float4*)mv)[t] = make_float4(a.x + bb.x + c.x + d.x, a.y + bb.y + c.y + d.y,
                                       a.z + bb.z + c.z + d.z, a.w + bb.w + c.w + d.w);
    }
    __syncthreads();
    red[r2][u] = k4; __syncthreads();
    if (t < 64) {
        float4 a = red[0][t], bb = red[1][t], c = red[2][t], d = red[3][t];
        ((float4*)(mv + C_))[t] = make_float4(a.x + bb.x + c.x + d.x, a.y + bb.y + c.y + d.y,
                                              a.z + bb.z + c.z + d.z, a.w + bb.w + c.w + d.w);
    }
    __syncthreads();
    red[r2][u] = v4; __syncthreads();
    if (t < 64) {
        float4 a = red[0][t], bb = red[1][t], c = red[2][t], d = red[3][t];
        ((float4*)(mv + 2 * C_))[t] = make_float4(a.x + bb.x + c.x + d.x, a.y + bb.y + c.y + d.y,
                                                  a.z + bb.z + c.z + d.z, a.w + bb.w + c.w + d.w);
    }

    cluster_sync_();

    // ---- B1: every block reduces q/k/v over the 8 segment partials ----
    {
        float qf = 0.f, kf = 0.f, vf = 0.f;
#pragma unroll
        for (int s2 = 0; s2 < 8; s2++) {
            const float* m2 = g_mv + (size_t)(b * 8 + s2) * 3 * C_;
            qf += m2[t]; kf += m2[C_ + t]; vf += m2[2 * C_ + t];
        }
        sh_q[t] = qf; sh_k[t] = kf; sh_v[t] = vf;
    }
    __syncthreads();

    // ---- B2: k min/max ----
    {
        float kk = sh_k[t];
        float mx = kk, mn = kk;
#pragma unroll
        for (int o = 16; o > 0; o >>= 1) {
            mx = fmaxf(mx, __shfl_xor_sync(0xffffffffu, mx, o));
            mn = fminf(mn, __shfl_xor_sync(0xffffffffu, mn, o));
        }
        if (lane == 0) { sh_mx[wid] = mx; sh_mn[wid] = mn; }
    }
    __syncthreads();
    if (t == 0) {
        float mx = sh_mx[0], mn = sh_mn[0];
        for (int i = 1; i < 8; i++) { mx = fmaxf(mx, sh_mx[i]); mn = fminf(mn, sh_mn[i]); }
        sh_scal[0] = mx; sh_scal[1] = mn;
    }
    __syncthreads();

    // ---- B3: channel softmax for this block's 32 rows (4 rows per warp) ----
    {
        float kmx = sh_scal[0], kmn = sh_scal[1];
        float c1[4], mb[4], num[4], den[4];
#pragma unroll
        for (int rr = 0; rr < 4; rr++) {
            float q = sh_q[seg * 32 + wid * 4 + rr];
            float m = (q >= 0.f) ? q * kmx : q * kmn;
            c1[rr] = q * LOG2E; mb[rr] = m * LOG2E;
            num[rr] = 0.f; den[rr] = 0.f;
        }
#pragma unroll
        for (int j = lane; j < C_; j += 32) {
            float kj = sh_k[j], vj = sh_v[j];
#pragma unroll
            for (int rr = 0; rr < 4; rr++) {
                float e = ex2f(fmaf(c1[rr], kj, -mb[rr]));
                den[rr] += e;
                num[rr] = fmaf(e, vj, num[rr]);
            }
        }
#pragma unroll
        for (int rr = 0; rr < 4; rr++) {
            float n = num[rr], d = den[rr];
#pragma unroll
            for (int o = 16; o > 0; o >>= 1) {
                n += __shfl_xor_sync(0xffffffffu, n, o);
                d += __shfl_xor_sync(0xffffffffu, d, o);
            }
            if (lane == 0) sh_att[wid * 4 + rr] = n / d;
        }
    }
    __syncthreads();

    // ---- B4: wp matvec partial over this block's 32 rows ----
    {
        float4 s4 = make_float4(0, 0, 0, 0);
#pragma unroll
        for (int i = 0; i < 8; i++) {
            int cl = r2 * 8 + i;
            int c  = seg * 32 + cl;
            float gg = sh_att[cl];
            float4 a = ((const float4*)(wp + (size_t)c * C_))[u];
            s4.x = fmaf(gg, a.x, s4.x); s4.y = fmaf(gg, a.y, s4.y);
            s4.z = fmaf(gg, a.z, s4.z); s4.w = fmaf(gg, a.w, s4.w);
        }
        __syncthreads();
        red[r2][u] = s4; __syncthreads();
        if (t < 64) {
            float4 a = red[0][t], bb = red[1][t], c = red[2][t], d = red[3][t];
            ((float4*)(g_wpp + (size_t)(b * 8 + seg) * C_))[t] =
                make_float4(a.x + bb.x + c.x + d.x, a.y + bb.y + c.y + d.y,
                            a.z + bb.z + c.z + d.z, a.w + bb.w + c.w + d.w);
        }
    }

    cluster_sync_();

    // ---- C: rank-0 block finalizes ----
    if (seg == 0) {
        float s = 0.f;
#pragma unroll
        for (int s2 = 0; s2 < 8; s2++) s += g_wpp[(size_t)(b * 8 + s2) * C_ + t];
        float cm = 1.0f / (1.0f + ex2f(-s * LOG2E));
        sh_cm[t] = cm;
        __syncthreads();
        int rank = 0;
#pragma unroll 8
        for (int j = 0; j < C_; j++) {
            float cj = sh_cm[j];
            rank += (cj < cm) || (cj == cm && j < t);
        }
        if (rank == 25) sh_scal[2] = cm;
        if (rank == 26) sh_scal[3] = cm;
        __syncthreads();
        float thr = 0.5f * (sh_scal[2] + sh_scal[3]);
        float pm  = (cm > thr) ? cm : 0.f;
        float rs  = rsqrtf(bn_v[t] + EPSF) * bn_g[t];
        float a   = (1.f + cm) * rs * pm;
        float d   = (bn_b[t] - bn_m[t] * rs) * pm;
#pragma unroll
        for (int f = 0; f < 3; f++) g_wf[(b * C_ + t) * 3 + f] = a * wqkv[t * 3 + f];
        sh_d[t] = d;
        __syncthreads();
        if (t < 3) {
            float cf = 0.f;
            for (int c = 0; c < C_; c++) cf = fmaf(sh_d[c], wqkv[c * 3 + t], cf);
            g_cf[b * 3 + t] = cf;
        }
    }
}

// ---------------------------------------------------------------------------
// K3: qkv projection, 8-lane-group per pixel. grid (128, B), 256 thr.
// ---------------------------------------------------------------------------
__global__ void __launch_bounds__(256, 4) k_qkv(const float* __restrict__ x) {
    __shared__ float4 swq[64], swk[64], swv[64];
    int b = blockIdx.y, t = threadIdx.x, lane = t & 31, wid = t >> 5;

    {
        float a = g_wf[b * C_ * 3 + t * 3 + 0];
        float k = g_wf[b * C_ * 3 + t * 3 + 1];
        float v = g_wf[b * C_ * 3 + t * 3 + 2];
        ((float*)swq)[t] = a; ((float*)swk)[t] = k; ((float*)swv)[t] = v;
    }
    __syncthreads();

    float cf0 = g_cf[b * 3 + 0], cf1 = g_cf[b * 3 + 1], cf2 = g_cf[b * 3 + 2];

    int g8 = lane >> 3, l8 = lane & 7;
    int p = (blockIdx.x * 8 + wid) * 4 + g8;
    const float4* x4 = (const float4*)(x + (size_t)b * N_ * C_);

    float q = 0.f, k = 0.f, v = 0.f;
#pragma unroll
    for (int j = 0; j < 8; j++) {
        float4 a  = x4[(size_t)p * 64 + j * 8 + l8];
        float4 wq4 = swq[j * 8 + l8];
        float4 wk4 = swk[j * 8 + l8];
        float4 wv4 = swv[j * 8 + l8];
        q = fmaf(a.x, wq4.x, q); k = fmaf(a.x, wk4.x, k); v = fmaf(a.x, wv4.x, v);
        q = fmaf(a.y, wq4.y, q); k = fmaf(a.y, wk4.y, k); v = fmaf(a.y, wv4.y, v);
        q = fmaf(a.z, wq4.z, q); k = fmaf(a.z, wk4.z, k); v = fmaf(a.z, wv4.z, v);
        q = fmaf(a.w, wq4.w, q); k = fmaf(a.w, wk4.w, k); v = fmaf(a.w, wv4.w, v);
    }
#pragma unroll
    for (int o = 4; o > 0; o >>= 1) {
        q += __shfl_xor_sync(0xffffffffu, q, o);
        k += __shfl_xor_sync(0xffffffffu, k, o);
        v += __shfl_xor_sync(0xffffffffu, v, o);
    }
    float kk = k + cf1;
    if (l8 == 0) {
        g_qs[b * N_ + p] = q + cf0;
        g_ks[b * N_ + p] = kk;
        g_vs[b * N_ + p] = v + cf2;
    }
    float lmax = kk, lmin = kk;
#pragma unroll
    for (int o = 16; o > 0; o >>= 1) {
        lmax = fmaxf(lmax, __shfl_xor_sync(0xffffffffu, lmax, o));
        lmin = fminf(lmin, __shfl_xor_sync(0xffffffffu, lmin, o));
    }
    if (lane == 0) {
        atomicMax(&g_kmax_u[b], encf(lmax));
        atomicMin(&g_kmin_u[b], encf(lmin));
    }
}

// ---------------------------------------------------------------------------
// K4: spatial softmax attention. grid (111, B) = 444 blocks (single wave,
// 3/SM). Warps 0-4: 5 rows, warps 5-7: 4 rows (37/blk). All-MUFU loop.
// ---------------------------------------------------------------------------
template <int NR>
__device__ __forceinline__ void attn_rows(const float4* skv4, int lane, int b, int i0,
                                          float kmx, float kmn, float* __restrict__ out) {
    float c1[NR], mb[NR], num[NR], den[NR], num2[NR], den2[NR];
#pragma unroll
    for (int s = 0; s < NR; s++) {
        int i = i0 + s;
        float qi = g_qs[b * N_ + ((i < N_) ? i : (N_ - 1))];
        float m  = (qi >= 0.f) ? qi * kmx : qi * kmn;
        c1[s] = qi * LOG2E; mb[s] = m * LOG2E;
        num[s] = 0.f; den[s] = 0.f; num2[s] = 0.f; den2[s] = 0.f;
    }
#pragma unroll 2
    for (int p = lane; p < N_ / 2; p += 32) {
        float4 kv = skv4[p];
#pragma unroll
        for (int s = 0; s < NR; s++) {
            float e0 = ex2f(fmaf(c1[s], kv.x, -mb[s]));
            den[s] += e0;
            num[s] = fmaf(e0, kv.y, num[s]);
            float e1 = ex2f(fmaf(c1[s], kv.z, -mb[s]));
            den2[s] += e1;
            num2[s] = fmaf(e1, kv.w, num2[s]);
        }
    }
#pragma unroll
    for (int s = 0; s < NR; s++) {
        float n = num[s] + num2[s], d = den[s] + den2[s];
#pragma unroll
        for (int o = 16; o > 0; o >>= 1) {
            n += __shfl_xor_sync(0xffffffffu, n, o);
            d += __shfl_xor_sync(0xffffffffu, d, o);
        }
        int i = i0 + s;
        if (lane == 0 && i < N_) out[b * N_ + i] = g_vs[b * N_ + i] + n / d;
    }
}

__global__ void __launch_bounds__(256) k_attn(float* __restrict__ out) {
    __shared__ float4 skv4[N_ / 2];
    int b = blockIdx.y, t = threadIdx.x, lane = t & 31, wid = t >> 5;

    const float2* kp = (const float2*)(g_ks + b * N_);
    const float2* vp = (const float2*)(g_vs + b * N_);
    for (int p = t; p < N_ / 2; p += 256) {
        float2 k2 = kp[p], v2 = vp[p];
        skv4[p] = make_float4(k2.x, v2.x, k2.y, v2.y);
    }
    __syncthreads();

    float kmx = decf(g_kmax_u[b]), kmn = decf(g_kmin_u[b]);
    int base = blockIdx.x * ARPB;

    if (wid < 5)
        attn_rows<5>(skv4, lane, b, base + wid * 5, kmx, kmn, out);
    else
        attn_rows<4>(skv4, lane, b, base + 25 + (wid - 5) * 4, kmx, kmn, out);
}

// ---------------------------------------------------------------------------
extern "C" void kernel_launch(void* const* d_in, const int* in_sizes, int n_in,
                              void* d_out, int out_size) {
    const float* x    = (const float*)d_in[0];
    const float* ca_g = (const float*)d_in[1];
    const float* ca_b = (const float*)d_in[2];
    const float* ca_m = (const float*)d_in[3];
    const float* ca_v = (const float*)d_in[4];
    const float* wq   = (const float*)d_in[5];
    const float* wk   = (const float*)d_in[6];
    const float* wv   = (const float*)d_in[7];
    const float* wp   = (const float*)d_in[8];
    const float* bn_g = (const float*)d_in[9];
    const float* bn_b = (const float*)d_in[10];
    const float* bn_m = (const float*)d_in[11];
    const float* bn_v = (const float*)d_in[12];
    const float* wqkv = (const float*)d_in[13];
    float* out = (float*)d_out;

    k_gap<<<dim3(GCH, B_), 256>>>(x, wq, wk, wv, wp);
    k_ch<<<dim3(8, B_), 256>>>(ca_g, ca_b, ca_m, ca_v, wq, wk, wv, wp,
                               bn_g, bn_b, bn_m, bn_v, wqkv);
    k_qkv<<<dim3(128, B_), 256>>>(x);
    k_attn<<<dim3(ABL, B_), 256>>>(out);
}